// round 6
// baseline (speedup 1.0000x reference)
#include <cuda_runtime.h>
#include <cstdint>

#define IN_CHN  128
#define OUT_CHN 128
#define HW      56
#define PHW     58
#define NB      32
#define NW_TOT  (OUT_CHN*IN_CHN*9)
#define SCALE_F 100.0f

// ---- device scratch ----
__device__ uint4 g_abits[NB * PHW * PHW];     // sign bits (1 = x<0)
__device__ uint4 g_vbits[NB * PHW * PHW];     // validity bits (1 = x!=0)
__device__ uint4 g_wbits[OUT_CHN * 9];        // weight sign bits [o][tap]

#define PACK_BLOCKS (NB * PHW)                // 1856
#define WB_BLOCKS   576

// single-instruction 3-input logic
template<int IMM>
__device__ __forceinline__ uint32_t lop3(uint32_t a, uint32_t b, uint32_t c) {
    uint32_t r;
    asm("lop3.b32 %0, %1, %2, %3, %4;" : "=r"(r) : "r"(a), "r"(b), "r"(c), "n"(IMM));
    return r;
}
#define TERM(a, w, v) lop3<0x28>(a, w, v)   // (a^w)&v
#define XOR3(a, b, c) lop3<0x96>(a, b, c)   // a^b^c
#define MAJ3(a, b, c) lop3<0xE8>(a, b, c)   // majority

// ============================================================
// Fused prep: activation pack + weight synthesis/pack
// ============================================================
__global__ void __launch_bounds__(256)
k_prep(const float* __restrict__ x,
       const float* __restrict__ M,
       const float* __restrict__ Z,
       const float* __restrict__ rv)
{
    int bid = blockIdx.x;
    int tid = threadIdx.x;

    if (bid < PACK_BLOCKS) {
        int b  = bid / PHW;
        int py = bid % PHW;
        int px = tid & 63;
        int q  = tid >> 6;
        if (px >= PHW) return;

        uint32_t aw = 0, vw = 0;
        if (py >= 1 && py <= HW && px >= 1 && px <= HW) {
            const float* xp = x + (size_t)b * IN_CHN * HW * HW
                                + (size_t)(q * 32) * (HW * HW)
                                + (py - 1) * HW + (px - 1);
#pragma unroll 8
            for (int c = 0; c < 32; c++) {
                float val = xp[(size_t)c * (HW * HW)];
                aw |= (val < 0.f)  ? (1u << c) : 0u;
                vw |= (val != 0.f) ? (1u << c) : 0u;
            }
        }
        int pidx = (b * PHW + py) * PHW + px;
        ((uint32_t*)g_abits)[pidx * 4 + q] = aw;
        ((uint32_t*)g_vbits)[pidx * 4 + q] = vw;
    } else {
        int gtid = (bid - PACK_BLOCKS) * 256 + tid;
        int wi   = gtid >> 5;
        int lane = gtid & 31;
        if (wi >= OUT_CHN * 9 * 4) return;

        int o = wi / 36;
        int r = wi % 36;
        int t = r >> 2;
        int j = r & 3;
        int i = j * 32 + lane;

        int idx = (o * IN_CHN + i) * 9 + t;
        float m = M[idx];
        float z[5];
        float s = 0.f;
#pragma unroll
        for (int k = 0; k < 5; k++) { z[k] = Z[k * NW_TOT + idx]; s += z[k] * z[k]; }
        float inv = rsqrtf(m * m + s / SCALE_F);
        float w = 0.f;
#pragma unroll
        for (int k = 0; k < 5; k++) w += rv[k] * (z[k] * inv);
        w += m * inv;

        unsigned bits = __ballot_sync(0xFFFFFFFFu, w < 0.f);
        if (lane == 0) ((uint32_t*)g_wbits)[wi] = bits;
    }
}

// ============================================================
// Conv: XNOR-popcount with 9-term carry-save compression.
// CTA = (y, b). 224 threads: strip = tid%28 (2 out px),
// og = tid/28 (8 groups x 16 o).
// Per (pixel, word): 9 tap terms -> 5 FAs -> 4 POPC.
// Weights staged in smem as [o][word j][tap 0..8, pad to 12].
// ============================================================
__global__ void __launch_bounds__(224, 2)
k_conv(const float* __restrict__ Alpha, float* __restrict__ out)
{
    __shared__ uint32_t wsm[OUT_CHN * 48];   // [o][j][12]
    __shared__ float alsm[OUT_CHN];

    int tid = threadIdx.x;
    int y   = blockIdx.x;
    int b   = blockIdx.y;

    // stage weights: transpose [o][t][j] -> [o][j][t]
    for (int k = tid; k < OUT_CHN * 9; k += 224) {
        uint4 w = g_wbits[k];
        int o = k / 9, t = k % 9;
        uint32_t* dst = &wsm[o * 48 + t];
        dst[0]  = w.x;
        dst[12] = w.y;
        dst[24] = w.z;
        dst[36] = w.w;
    }
    if (tid < OUT_CHN) alsm[tid] = Alpha[tid];
    __syncthreads();

    int xp = tid % 28;
    int og = tid / 28;
    int x0 = xp * 2;

    uint32_t a[3][4][4], v[3][4][4];
    int vsum0 = 0, vsum1 = 0;
#pragma unroll
    for (int r = 0; r < 3; r++) {
#pragma unroll
        for (int c = 0; c < 4; c++) {
            int pidx = (b * PHW + (y + r)) * PHW + (x0 + c);
            uint4 ua = g_abits[pidx];
            uint4 uv = g_vbits[pidx];
            a[r][c][0] = ua.x; a[r][c][1] = ua.y; a[r][c][2] = ua.z; a[r][c][3] = ua.w;
            v[r][c][0] = uv.x; v[r][c][1] = uv.y; v[r][c][2] = uv.z; v[r][c][3] = uv.w;
            int pv = __popc(uv.x) + __popc(uv.y) + __popc(uv.z) + __popc(uv.w);
            if (c < 3) vsum0 += pv;
            if (c > 0) vsum1 += pv;
        }
    }

    float* outp = out + ((size_t)b * OUT_CHN) * (HW * HW) + y * HW + x0;

#pragma unroll 1
    for (int oi = 0; oi < 16; oi++) {
        int o = og * 16 + oi;
        const uint32_t* wrow = &wsm[o * 48];

        int acc0 = 0, acc1 = 0;
#pragma unroll
        for (int j = 0; j < 4; j++) {
            // 9 tap words for this channel-word
            uint4 wA = *(const uint4*)(wrow + j * 12);       // taps 0..3
            uint4 wB = *(const uint4*)(wrow + j * 12 + 4);   // taps 4..7
            uint32_t w8 = wrow[j * 12 + 8];                  // tap 8
            uint32_t wt[9] = {wA.x, wA.y, wA.z, wA.w, wB.x, wB.y, wB.z, wB.w, w8};

#pragma unroll
            for (int p = 0; p < 2; p++) {
                // terms t = rg*3+dx uses a[rg][dx+p][j]
                uint32_t t0 = TERM(a[0][p + 0][j], wt[0], v[0][p + 0][j]);
                uint32_t t1 = TERM(a[0][p + 1][j], wt[1], v[0][p + 1][j]);
                uint32_t t2 = TERM(a[0][p + 2][j], wt[2], v[0][p + 2][j]);
                uint32_t t3 = TERM(a[1][p + 0][j], wt[3], v[1][p + 0][j]);
                uint32_t t4 = TERM(a[1][p + 1][j], wt[4], v[1][p + 1][j]);
                uint32_t t5 = TERM(a[1][p + 2][j], wt[5], v[1][p + 2][j]);
                uint32_t t6 = TERM(a[2][p + 0][j], wt[6], v[2][p + 0][j]);
                uint32_t t7 = TERM(a[2][p + 1][j], wt[7], v[2][p + 1][j]);
                uint32_t t8 = TERM(a[2][p + 2][j], wt[8], v[2][p + 2][j]);

                uint32_t s1 = XOR3(t0, t1, t2), c1 = MAJ3(t0, t1, t2);
                uint32_t s2 = XOR3(t3, t4, t5), c2 = MAJ3(t3, t4, t5);
                uint32_t s3 = XOR3(t6, t7, t8), c3 = MAJ3(t6, t7, t8);

                uint32_t S  = XOR3(s1, s2, s3), Cs = MAJ3(s1, s2, s3);
                uint32_t Sc = XOR3(c1, c2, c3), Cc = MAJ3(c1, c2, c3);

                int p0 = __popc(S);
                int p1 = __popc(Cs) + __popc(Sc);
                int p2 = __popc(Cc);
                int add = p0 + 2 * p1 + 4 * p2;
                if (p == 0) acc0 += add; else acc1 += add;
            }
        }
        float al = alsm[o];
        float2 res;
        res.x = al * (float)(vsum0 - 2 * acc0);
        res.y = al * (float)(vsum1 - 2 * acc1);
        *(float2*)(outp + (size_t)o * (HW * HW)) = res;
    }
}

// ============================================================
extern "C" void kernel_launch(void* const* d_in, const int* in_sizes, int n_in,
                              void* d_out, int out_size)
{
    const float* x     = (const float*)d_in[0];
    const float* Alpha = (const float*)d_in[1];
    const float* M     = (const float*)d_in[2];
    const float* Z     = (const float*)d_in[3];
    const float* rv    = (const float*)d_in[4];
    float* out = (float*)d_out;

    k_prep<<<PACK_BLOCKS + WB_BLOCKS, 256>>>(x, M, Z, rv);
    k_conv<<<dim3(HW, NB), 224>>>(Alpha, out);
}

// round 7
// speedup vs baseline: 1.1078x; 1.1078x over previous
#include <cuda_runtime.h>
#include <cstdint>

#define IN_CHN  128
#define OUT_CHN 128
#define HW      56
#define PHW     58
#define NB      32
#define NPIX    (NB * PHW * PHW)
#define NW_TOT  (OUT_CHN*IN_CHN*9)
#define SCALE_F 100.0f

// ---- device scratch: SoA word-planes for coalesced per-j loads ----
__device__ uint32_t g_a[4 * NPIX];            // sign bits, plane j
__device__ uint32_t g_v[4 * NPIX];            // validity bits, plane j
__device__ uint4    g_wbits[OUT_CHN * 9];     // weight sign bits [o][tap]

#define PACK_BLOCKS (NB * PHW)                // 1856
#define WB_BLOCKS   576

template<int IMM>
__device__ __forceinline__ uint32_t lop3(uint32_t a, uint32_t b, uint32_t c) {
    uint32_t r;
    asm("lop3.b32 %0, %1, %2, %3, %4;" : "=r"(r) : "r"(a), "r"(b), "r"(c), "n"(IMM));
    return r;
}
#define TERM(a, w, v) lop3<0x28>(a, w, v)   // (a^w)&v
#define XOR3(a, b, c) lop3<0x96>(a, b, c)
#define MAJ3(a, b, c) lop3<0xE8>(a, b, c)

// ============================================================
// Fused prep: activation pack (SoA planes) + weight synthesis
// ============================================================
__global__ void __launch_bounds__(256)
k_prep(const float* __restrict__ x,
       const float* __restrict__ M,
       const float* __restrict__ Z,
       const float* __restrict__ rv)
{
    int bid = blockIdx.x;
    int tid = threadIdx.x;

    if (bid < PACK_BLOCKS) {
        int b  = bid / PHW;
        int py = bid % PHW;
        int px = tid & 63;
        int q  = tid >> 6;          // word plane 0..3
        if (px >= PHW) return;

        uint32_t aw = 0, vw = 0;
        if (py >= 1 && py <= HW && px >= 1 && px <= HW) {
            const float* xp = x + (size_t)b * IN_CHN * HW * HW
                                + (size_t)(q * 32) * (HW * HW)
                                + (py - 1) * HW + (px - 1);
#pragma unroll 8
            for (int c = 0; c < 32; c++) {
                float val = xp[(size_t)c * (HW * HW)];
                aw |= (val < 0.f)  ? (1u << c) : 0u;
                vw |= (val != 0.f) ? (1u << c) : 0u;
            }
        }
        int pidx = (b * PHW + py) * PHW + px;
        g_a[q * NPIX + pidx] = aw;
        g_v[q * NPIX + pidx] = vw;
    } else {
        int gtid = (bid - PACK_BLOCKS) * 256 + tid;
        int wi   = gtid >> 5;
        int lane = gtid & 31;
        if (wi >= OUT_CHN * 9 * 4) return;

        int o = wi / 36;
        int r = wi % 36;
        int t = r >> 2;
        int j = r & 3;
        int i = j * 32 + lane;

        int idx = (o * IN_CHN + i) * 9 + t;
        float m = M[idx];
        float z[5];
        float s = 0.f;
#pragma unroll
        for (int k = 0; k < 5; k++) { z[k] = Z[k * NW_TOT + idx]; s += z[k] * z[k]; }
        float inv = rsqrtf(m * m + s / SCALE_F);
        float w = 0.f;
#pragma unroll
        for (int k = 0; k < 5; k++) w += rv[k] * (z[k] * inv);
        w += m * inv;

        unsigned bits = __ballot_sync(0xFFFFFFFFu, w < 0.f);
        if (lane == 0) ((uint32_t*)g_wbits)[wi] = bits;
    }
}

// ============================================================
// Conv: XNOR-popcount, 3-row FA compression (R5 scheme),
// restructured j-outer / o-inner for low register pressure.
// CTA = (y, b). 224 threads: strip = tid%28 (2 out px),
// og = tid/28 (8 groups x 16 o). acc[16][2] persists across j.
// ============================================================
__global__ void __launch_bounds__(224, 3)
k_conv(const float* __restrict__ Alpha, float* __restrict__ out)
{
    __shared__ uint32_t wsm[4][OUT_CHN * 12];   // [j][o*12 + tap]
    __shared__ float alsm[OUT_CHN];

    int tid = threadIdx.x;
    int y   = blockIdx.x;
    int b   = blockIdx.y;

    // stage weights as word-planes
    for (int k = tid; k < OUT_CHN * 9; k += 224) {
        uint4 w = g_wbits[k];
        int o = k / 9, t = k % 9;
        wsm[0][o * 12 + t] = w.x;
        wsm[1][o * 12 + t] = w.y;
        wsm[2][o * 12 + t] = w.z;
        wsm[3][o * 12 + t] = w.w;
    }
    if (tid < OUT_CHN) alsm[tid] = Alpha[tid];
    __syncthreads();

    int xp = tid % 28;
    int og = tid / 28;
    int x0 = xp * 2;

    int pidx0 = (b * PHW + y) * PHW + x0;

    int acc0[16], acc1[16];
#pragma unroll
    for (int i = 0; i < 16; i++) { acc0[i] = 0; acc1[i] = 0; }
    int vsum0 = 0, vsum1 = 0;

#pragma unroll 1
    for (int j = 0; j < 4; j++) {
        const uint32_t* ap = g_a + j * NPIX;
        const uint32_t* vp = g_v + j * NPIX;

        uint32_t a[3][4], v[3][4];
#pragma unroll
        for (int r = 0; r < 3; r++) {
#pragma unroll
            for (int c = 0; c < 4; c++) {
                int pidx = pidx0 + r * PHW + c;
                a[r][c] = ap[pidx];
                v[r][c] = vp[pidx];
                int pv = __popc(v[r][c]);
                if (c < 3) vsum0 += pv;
                if (c > 0) vsum1 += pv;
            }
        }

        const uint32_t* wj = wsm[j];
#pragma unroll
        for (int oi = 0; oi < 16; oi++) {
            int o = og * 16 + oi;
            const uint32_t* wr = wj + o * 12;
            uint4 wA = *(const uint4*)(wr);       // taps 0..3
            uint4 wB = *(const uint4*)(wr + 4);   // taps 4..7
            uint32_t w8 = wr[8];
            uint32_t wt[9] = {wA.x, wA.y, wA.z, wA.w, wB.x, wB.y, wB.z, wB.w, w8};

            int p0 = 0, p1 = 0;
#pragma unroll
            for (int rg = 0; rg < 3; rg++) {
                // pixel 0: cols 0,1,2
                uint32_t t0 = TERM(a[rg][0], wt[rg * 3 + 0], v[rg][0]);
                uint32_t t1 = TERM(a[rg][1], wt[rg * 3 + 1], v[rg][1]);
                uint32_t t2 = TERM(a[rg][2], wt[rg * 3 + 2], v[rg][2]);
                uint32_t xs = XOR3(t0, t1, t2);
                uint32_t xc = MAJ3(t0, t1, t2);
                p0 += __popc(xs) + 2 * __popc(xc);
                // pixel 1: cols 1,2,3
                uint32_t u0 = TERM(a[rg][1], wt[rg * 3 + 0], v[rg][1]);
                uint32_t u1 = TERM(a[rg][2], wt[rg * 3 + 1], v[rg][2]);
                uint32_t u2 = TERM(a[rg][3], wt[rg * 3 + 2], v[rg][3]);
                uint32_t ys = XOR3(u0, u1, u2);
                uint32_t yc = MAJ3(u0, u1, u2);
                p1 += __popc(ys) + 2 * __popc(yc);
            }
            acc0[oi] += p0;
            acc1[oi] += p1;
        }
    }

    float* outp = out + ((size_t)b * OUT_CHN) * (HW * HW) + y * HW + x0;
#pragma unroll
    for (int oi = 0; oi < 16; oi++) {
        int o = og * 16 + oi;
        float al = alsm[o];
        float2 res;
        res.x = al * (float)(vsum0 - 2 * acc0[oi]);
        res.y = al * (float)(vsum1 - 2 * acc1[oi]);
        *(float2*)(outp + (size_t)o * (HW * HW)) = res;
    }
}

// ============================================================
extern "C" void kernel_launch(void* const* d_in, const int* in_sizes, int n_in,
                              void* d_out, int out_size)
{
    const float* x     = (const float*)d_in[0];
    const float* Alpha = (const float*)d_in[1];
    const float* M     = (const float*)d_in[2];
    const float* Z     = (const float*)d_in[3];
    const float* rv    = (const float*)d_in[4];
    float* out = (float*)d_out;

    k_prep<<<PACK_BLOCKS + WB_BLOCKS, 256>>>(x, M, Z, rv);
    k_conv<<<dim3(HW, NB), 224>>>(Alpha, out);
}